// round 2
// baseline (speedup 1.0000x reference)
#include <cuda_runtime.h>
#include <cuda_bf16.h>

// ---------------- problem constants ----------------
#define BB   256
#define PP   196
#define ENC  2048
#define VV   10000
#define EE   512
#define HH   512
#define AA   512
#define SS   54
#define TT   53
#define KG   2560            // E + ENC (gates input K)
#define OUT_PRED_OFF (BB + BB*SS)   // 256 + 13824 = 14080

// ---------------- device scratch (static, no allocation) ----------------
__device__ int   g_order[BB];
__device__ int   g_predlen[BB];
__device__ int   g_caps[BB*SS];
__device__ float g_bias_gates[4*HH];            // b_ih + b_hh
__device__ float g_mean[BB*ENC];
__device__ float g_h[BB*HH];
__device__ float g_c[BB*HH];
__device__ float g_hnew[BB*HH];
__device__ float g_hidatt[BB*AA];
__device__ float g_gs[BB*ENC];
__device__ float g_alpha[BB*PP];
__device__ float g_gatesin[BB*KG];              // [x_t | gated ctx]
__device__ float g_gates[BB*4*HH];
__device__ float g_encatt[(size_t)BB*PP*AA];    // original image order, 102.8 MB

__device__ __forceinline__ float sigf(float x) { return 1.f / (1.f + expf(-x)); }

// ---------------- setup: stable descending counting sort + outputs ----------------
// captions / caption_lengths may be int32 (JAX x64 disabled) or int64.
// Detect: lengths are always >= 2, so an int64 buffer viewed as int32 has
// zeros at odd indices.
__global__ void setup_kernel(const int* __restrict__ caps32,
                             const int* __restrict__ lens32,
                             const float* __restrict__ b_ih,
                             const float* __restrict__ b_hh,
                             float* __restrict__ out)
{
    __shared__ int s_order[BB];
    __shared__ int s_is64;
    int tid = threadIdx.x;
    if (tid == 0) {
        int is64 = (lens32[1] == 0 && lens32[3] == 0 && lens32[5] == 0) ? 1 : 0;
        s_is64 = is64;
        int cnt[64];
        for (int i = 0; i < 64; i++) cnt[i] = 0;
        for (int i = 0; i < BB; i++) {
            int l = is64 ? lens32[2*i] : lens32[i];
            l = max(0, min(63, l));
            cnt[l]++;
        }
        int start[64]; int run = 0;
        for (int l = 63; l >= 0; l--) { start[l] = run; run += cnt[l]; }
        for (int i = 0; i < BB; i++) {
            int l = is64 ? lens32[2*i] : lens32[i];
            l = max(0, min(63, l));
            s_order[start[l]++] = i;
        }
    }
    __syncthreads();
    int is64 = s_is64;
    int b = tid;
    int ord = s_order[b];
    g_order[b] = ord;
    int len = is64 ? lens32[2*ord] : lens32[ord];
    len = max(1, min(SS, len));
    int pl = len - 1;
    g_predlen[b] = pl;
    out[b] = (float)pl;
    for (int s = 0; s < SS; s++) {
        size_t idx = (size_t)ord * SS + s;
        int cap = is64 ? caps32[2*idx] : caps32[idx];
        out[BB + b*SS + s] = (float)cap;
        cap = max(0, min(VV - 1, cap));
        g_caps[b*SS + s] = cap;
    }
    for (int j = tid; j < 4*HH; j += BB) g_bias_gates[j] = b_ih[j] + b_hh[j];
}

// ---------------- mean over pixels ----------------
__global__ void mean_kernel(const float* __restrict__ img)
{
    int b  = blockIdx.y;
    int ch = blockIdx.x * 256 + threadIdx.x;
    int ord = g_order[b];
    const float* base = img + (size_t)ord * PP * ENC + ch;
    float acc = 0.f;
#pragma unroll 4
    for (int p = 0; p < PP; p++) acc += base[(size_t)p * ENC];
    g_mean[b*ENC + ch] = acc * (1.0f / (float)PP);
}

// ---------------- generic SGEMM: C[m,n] = sum_k A[m,k]*W[n,k] (+bias) ----------------
// A: M x K row-major (lda = K).  W: N x K row-major.  BN = 64, BK = 16, 256 threads.
// EPI: 0 = plain store, 1 = sigmoid store, 2 = store logits into out (masked rows).
// MASKED: early-exit whole block if the first (most-active) row is inactive.
template<int BM, int EPI, bool ACCUM, bool MASKED>
__global__ void sgemm_nt(const float* __restrict__ A, const float* __restrict__ W,
                         const float* __restrict__ bias, float* __restrict__ C,
                         int M, int N, int K, int t, float* __restrict__ outbase)
{
    constexpr int TM = BM / 16;
    const int m0 = blockIdx.y * BM;
    const int n0 = blockIdx.x * 64;
    if (MASKED && g_predlen[m0] <= t) return;

    __shared__ __align__(16) float As[2][16][BM + 4];
    __shared__ __align__(16) float Ws[2][16][68];

    const int tid = threadIdx.x;
    const int lr  = tid >> 2;         // 0..63
    const int lk  = (tid & 3) << 2;   // 0,4,8,12
    const int ty  = tid >> 4;         // 0..15
    const int tx  = tid & 15;         // 0..15

    float acc[TM][4];
#pragma unroll
    for (int i = 0; i < TM; i++)
#pragma unroll
        for (int j = 0; j < 4; j++) acc[i][j] = 0.f;

    float4 a_st[BM / 64];
    float4 w_st;

    auto g_load = [&](int k0) {
#pragma unroll
        for (int rr = 0; rr < BM/64; rr++)
            a_st[rr] = *(const float4*)(A + (size_t)(m0 + rr*64 + lr) * K + k0 + lk);
        int n = n0 + lr;
        w_st = (n < N) ? *(const float4*)(W + (size_t)n * K + k0 + lk)
                       : make_float4(0.f, 0.f, 0.f, 0.f);
    };
    auto s_store = [&](int buf) {
#pragma unroll
        for (int rr = 0; rr < BM/64; rr++) {
            As[buf][lk+0][rr*64+lr] = a_st[rr].x;
            As[buf][lk+1][rr*64+lr] = a_st[rr].y;
            As[buf][lk+2][rr*64+lr] = a_st[rr].z;
            As[buf][lk+3][rr*64+lr] = a_st[rr].w;
        }
        Ws[buf][lk+0][lr] = w_st.x;
        Ws[buf][lk+1][lr] = w_st.y;
        Ws[buf][lk+2][lr] = w_st.z;
        Ws[buf][lk+3][lr] = w_st.w;
    };

    g_load(0);
    s_store(0);
    __syncthreads();

    int cur = 0;
    for (int k0 = 0; k0 < K; k0 += 16) {
        bool more = (k0 + 16 < K);
        if (more) g_load(k0 + 16);
#pragma unroll
        for (int kk = 0; kk < 16; kk++) {
            float wr[4];
            *(float4*)wr = *(const float4*)&Ws[cur][kk][tx*4];
#pragma unroll
            for (int i4 = 0; i4 < TM; i4 += 4) {
                float ar[4];
                *(float4*)ar = *(const float4*)&As[cur][kk][ty*TM + i4];
#pragma unroll
                for (int ii = 0; ii < 4; ii++)
#pragma unroll
                    for (int j = 0; j < 4; j++)
                        acc[i4+ii][j] = fmaf(ar[ii], wr[j], acc[i4+ii][j]);
            }
        }
        if (more) { s_store(cur ^ 1); cur ^= 1; }
        __syncthreads();
    }

#pragma unroll
    for (int i = 0; i < TM; i++) {
        int m = m0 + ty*TM + i;
        bool rowon = true;
        if (EPI == 2) rowon = (g_predlen[m] > t);
#pragma unroll
        for (int j = 0; j < 4; j++) {
            int n = n0 + tx*4 + j;
            if (n < N) {
                float v = acc[i][j];
                if (bias) v += bias[n];
                if (EPI == 1) v = sigf(v);
                if (ACCUM)          C[(size_t)m * N + n] += v;
                else if (EPI == 2) { if (rowon) outbase[((size_t)m * TT + t) * VV + n] = v; }
                else                C[(size_t)m * N + n] = v;
            }
        }
    }
}

// ---------------- x_t gather ----------------
__global__ void xt_kernel(const float* __restrict__ emb, int t)
{
    int b = blockIdx.x;
    if (g_predlen[b] <= t) return;
    int cap = g_caps[b*SS + t];
    g_gatesin[(size_t)b*KG + threadIdx.x] = emb[(size_t)cap * EE + threadIdx.x];
}

// ---------------- fused attention scores + softmax ----------------
__global__ void attn_kernel(const float* __restrict__ fw, const float* __restrict__ fb, int t)
{
    int b = blockIdx.x;
    if (g_predlen[b] <= t) return;
    __shared__ float s_fw[AA], s_hid[AA], s_e[200], s_r[8];
    int tid = threadIdx.x;
    s_fw[tid]       = fw[tid];
    s_fw[tid + 256] = fw[tid + 256];
    s_hid[tid]       = g_hidatt[b*AA + tid];
    s_hid[tid + 256] = g_hidatt[b*AA + tid + 256];
    __syncthreads();

    int warp = tid >> 5, lane = tid & 31;
    int ord = g_order[b];
    const float* base = g_encatt + (size_t)ord * PP * AA;
    for (int p = warp; p < PP; p += 8) {
        const float* row = base + (size_t)p * AA;
        float acc = 0.f;
#pragma unroll
        for (int a = lane; a < AA; a += 32)
            acc += fmaxf(row[a] + s_hid[a], 0.f) * s_fw[a];
        for (int o = 16; o; o >>= 1) acc += __shfl_xor_sync(0xFFFFFFFFu, acc, o);
        if (!lane) s_e[p] = acc;
    }
    __syncthreads();

    float fbv = fb[0];
    float v = (tid < PP) ? (s_e[tid] + fbv) : -1e30f;
    float m = v;
    for (int o = 16; o; o >>= 1) m = fmaxf(m, __shfl_xor_sync(0xFFFFFFFFu, m, o));
    if (!lane) s_r[warp] = m;
    __syncthreads();
    float bm = s_r[0];
    for (int i = 1; i < 8; i++) bm = fmaxf(bm, s_r[i]);
    __syncthreads();
    float ex = (tid < PP) ? expf(v - bm) : 0.f;
    float sm = ex;
    for (int o = 16; o; o >>= 1) sm += __shfl_xor_sync(0xFFFFFFFFu, sm, o);
    if (!lane) s_r[warp] = sm;
    __syncthreads();
    float bs = 0.f;
    for (int i = 0; i < 8; i++) bs += s_r[i];
    if (tid < PP) g_alpha[b*PP + tid] = ex / bs;
}

// ---------------- context einsum (gated), writes into gates input ----------------
__global__ void ctx_kernel(const float* __restrict__ img, int t)
{
    int b = blockIdx.y;
    if (g_predlen[b] <= t) return;
    __shared__ float s_a[PP];
    int tid = threadIdx.x;
    if (tid < PP) s_a[tid] = g_alpha[b*PP + tid];
    __syncthreads();
    int c = blockIdx.x * 256 + tid;
    int ord = g_order[b];
    const float* base = img + (size_t)ord * PP * ENC + c;
    float acc = 0.f;
#pragma unroll 4
    for (int p = 0; p < PP; p++) acc += s_a[p] * base[(size_t)p * ENC];
    g_gatesin[(size_t)b*KG + EE + c] = acc * g_gs[b*ENC + c];
}

// ---------------- LSTM cell (masked state update) ----------------
__global__ void cell_kernel(int t)
{
    int b = blockIdx.x;
    if (g_predlen[b] <= t) return;
    int j = threadIdx.x;
    const float* g = g_gates + (size_t)b * 4*HH;
    float ig = sigf(g[j]);
    float fg = sigf(g[j + HH]);
    float gg = tanhf(g[j + 2*HH]);
    float og = sigf(g[j + 3*HH]);
    float c  = fg * g_c[b*HH + j] + ig * gg;
    float h  = og * tanhf(c);
    g_c[b*HH + j] = c;
    g_h[b*HH + j] = h;
    g_hnew[b*HH + j] = h;
}

// ---------------- launch ----------------
extern "C" void kernel_launch(void* const* d_in, const int* in_sizes, int n_in,
                              void* d_out, int out_size)
{
    const float* img   = (const float*)d_in[0];
    const int*   caps  = (const int*)d_in[1];     // int32 or int64 (auto-detected)
    const int*   clen  = (const int*)d_in[2];
    const float* emb   = (const float*)d_in[3];
    const float* W_ih  = (const float*)d_in[4];
    const float* W_hh  = (const float*)d_in[5];
    const float* b_ih  = (const float*)d_in[6];
    const float* b_hh  = (const float*)d_in[7];
    const float* ec_w  = (const float*)d_in[8];
    const float* ec_b  = (const float*)d_in[9];
    const float* eh_w  = (const float*)d_in[10];
    const float* eh_b  = (const float*)d_in[11];
    const float* sag_w = (const float*)d_in[12];
    const float* sag_b = (const float*)d_in[13];
    const float* ae_w  = (const float*)d_in[14];
    const float* ae_b  = (const float*)d_in[15];
    const float* ah_w  = (const float*)d_in[16];
    const float* ah_b  = (const float*)d_in[17];
    const float* af_w  = (const float*)d_in[18];
    const float* af_b  = (const float*)d_in[19];
    const float* fc_w  = (const float*)d_in[20];
    const float* fc_b  = (const float*)d_in[21];
    float* out = (float*)d_out;

    float *p_mean, *p_h, *p_c, *p_hid, *p_gs, *p_gin, *p_gates, *p_hnew, *p_encatt, *p_bg;
    cudaGetSymbolAddress((void**)&p_mean,   g_mean);
    cudaGetSymbolAddress((void**)&p_h,      g_h);
    cudaGetSymbolAddress((void**)&p_c,      g_c);
    cudaGetSymbolAddress((void**)&p_hid,    g_hidatt);
    cudaGetSymbolAddress((void**)&p_gs,     g_gs);
    cudaGetSymbolAddress((void**)&p_gin,    g_gatesin);
    cudaGetSymbolAddress((void**)&p_gates,  g_gates);
    cudaGetSymbolAddress((void**)&p_hnew,   g_hnew);
    cudaGetSymbolAddress((void**)&p_encatt, g_encatt);
    cudaGetSymbolAddress((void**)&p_bg,     g_bias_gates);

    // zero the whole output once: coefs stay 0, inactive preds stay 0
    cudaMemsetAsync(d_out, 0, (size_t)out_size * sizeof(float));

    setup_kernel<<<1, 256>>>(caps, clen, b_ih, b_hh, out);
    mean_kernel<<<dim3(ENC/256, BB), 256>>>(img);

    // h0 / c0
    sgemm_nt<64,0,false,false><<<dim3(HH/64, BB/64), 256>>>(p_mean, eh_w, eh_b, p_h, BB, HH, ENC, 0, nullptr);
    sgemm_nt<64,0,false,false><<<dim3(HH/64, BB/64), 256>>>(p_mean, ec_w, ec_b, p_c, BB, HH, ENC, 0, nullptr);

    // enc_att precompute (original image order)
    sgemm_nt<128,0,false,false><<<dim3(AA/64, (BB*PP)/128), 256>>>(img, ae_w, ae_b, p_encatt,
                                                                   BB*PP, AA, ENC, 0, nullptr);

    for (int t = 0; t < TT; t++) {
        // hid_att = h @ att_h_w^T + b
        sgemm_nt<64,0,false,true><<<dim3(AA/64, BB/64), 256>>>(p_h, ah_w, ah_b, p_hid, BB, AA, HH, t, nullptr);
        // gs = sigmoid(h @ sag_w^T + b)
        sgemm_nt<64,1,false,true><<<dim3(ENC/64, BB/64), 256>>>(p_h, sag_w, sag_b, p_gs, BB, ENC, HH, t, nullptr);
        // x_t gather
        xt_kernel<<<BB, EE>>>(emb, t);
        // attention scores + softmax
        attn_kernel<<<BB, 256>>>(af_w, af_b, t);
        // gated context into gates input
        ctx_kernel<<<dim3(ENC/256, BB), 256>>>(img, t);
        // gates = [x|ctx] @ W_ih^T + (b_ih+b_hh)
        sgemm_nt<64,0,false,true><<<dim3((4*HH)/64, BB/64), 256>>>(p_gin, W_ih, p_bg, p_gates, BB, 4*HH, KG, t, nullptr);
        // gates += h @ W_hh^T
        sgemm_nt<64,0,true ,true><<<dim3((4*HH)/64, BB/64), 256>>>(p_h, W_hh, nullptr, p_gates, BB, 4*HH, HH, t, nullptr);
        // LSTM cell
        cell_kernel<<<BB, HH>>>(t);
        // logits -> preds (active rows only; rest pre-zeroed)
        sgemm_nt<64,2,false,true><<<dim3((VV+63)/64, BB/64), 256>>>(p_hnew, fc_w, fc_b, nullptr, BB, VV, HH, t,
                                                                    out + OUT_PRED_OFF);
    }
}

// round 3
// speedup vs baseline: 1.3027x; 1.3027x over previous
#include <cuda_runtime.h>
#include <cuda_bf16.h>
#include <cstdint>

// ---------------- problem constants ----------------
#define BB   256
#define PP   196
#define ENC  2048
#define VV   10000
#define EE   512
#define HH   512
#define AA   512
#define SS   54
#define TT   53
#define KG   2560            // E + ENC
#define KGX  3072            // E + ENC + H (gates input K, h appended)
#define OUT_PRED_OFF (BB + BB*SS)

// ---------------- device scratch ----------------
__device__ int   g_order[BB];
__device__ int   g_predlen[BB];
__device__ int   g_caps[BB*SS];
__device__ float g_bias_gates[4*HH];            // b_ih + b_hh
__device__ float g_bias_fused[KG];              // [ah_b | sag_b]
__device__ float g_mean[BB*ENC];
__device__ float g_h[BB*HH];
__device__ float g_c[BB*HH];
__device__ float g_hnew[BB*HH];
__device__ float g_hidatt[BB*AA];
__device__ float g_gs[BB*ENC];
__device__ float g_alpha[BB*PP];
__device__ float g_gatesin[(size_t)BB*KGX];     // [x_t | gated ctx | h]
__device__ float g_gates[BB*4*HH];
__device__ float g_Wg[(size_t)(4*HH)*KGX];      // [W_ih | W_hh], 2048 x 3072
__device__ float g_Whg[(size_t)KG*HH];          // [att_h_w ; sag_w], 2560 x 512
__device__ float g_encatt[(size_t)BB*PP*AA];    // 102.8 MB

__device__ __forceinline__ float sigf(float x) { return 1.f / (1.f + expf(-x)); }

__device__ __forceinline__ uint32_t f2tf32(float x) {
    uint32_t u;
    asm("cvt.rna.tf32.f32 %0, %1;" : "=r"(u) : "f"(x));
    return u;
}

__device__ __forceinline__ void mma_tf32(float4& d, const uint32_t a[4], const uint32_t b[2]) {
    asm volatile(
        "mma.sync.aligned.m16n8k8.row.col.f32.tf32.tf32.f32 "
        "{%0,%1,%2,%3}, {%4,%5,%6,%7}, {%8,%9}, {%0,%1,%2,%3};\n"
        : "+f"(d.x), "+f"(d.y), "+f"(d.z), "+f"(d.w)
        : "r"(a[0]), "r"(a[1]), "r"(a[2]), "r"(a[3]), "r"(b[0]), "r"(b[1]));
}

// swizzled smem index: row stride 72, col xor by k-group (conflict-free ld+st)
#define IDX(k, m) ((k)*72 + ((m) ^ ((((k) >> 2) & 3) << 3)))

// ---------------- setup ----------------
__global__ void setup_kernel(const int* __restrict__ caps32,
                             const int* __restrict__ lens32,
                             const float* __restrict__ b_ih,
                             const float* __restrict__ b_hh,
                             float* __restrict__ out)
{
    __shared__ int s_order[BB];
    __shared__ int s_is64;
    int tid = threadIdx.x;
    if (tid == 0) {
        int is64 = (lens32[1] == 0 && lens32[3] == 0 && lens32[5] == 0) ? 1 : 0;
        s_is64 = is64;
        int cnt[64];
        for (int i = 0; i < 64; i++) cnt[i] = 0;
        for (int i = 0; i < BB; i++) {
            int l = is64 ? lens32[2*i] : lens32[i];
            l = max(0, min(63, l));
            cnt[l]++;
        }
        int start[64]; int run = 0;
        for (int l = 63; l >= 0; l--) { start[l] = run; run += cnt[l]; }
        for (int i = 0; i < BB; i++) {
            int l = is64 ? lens32[2*i] : lens32[i];
            l = max(0, min(63, l));
            s_order[start[l]++] = i;
        }
    }
    __syncthreads();
    int is64 = s_is64;
    int b = tid;
    int ord = s_order[b];
    g_order[b] = ord;
    int len = is64 ? lens32[2*ord] : lens32[ord];
    len = max(1, min(SS, len));
    int pl = len - 1;
    g_predlen[b] = pl;
    out[b] = (float)pl;
    for (int s = 0; s < SS; s++) {
        size_t idx = (size_t)ord * SS + s;
        int cap = is64 ? caps32[2*idx] : caps32[idx];
        out[BB + b*SS + s] = (float)cap;
        cap = max(0, min(VV - 1, cap));
        g_caps[b*SS + s] = cap;
    }
    for (int j = tid; j < 4*HH; j += BB) g_bias_gates[j] = b_ih[j] + b_hh[j];
}

// combined gates weight [W_ih | W_hh] : 2048 x 3072
__global__ void build_wg(const float* __restrict__ W_ih, const float* __restrict__ W_hh)
{
    int n = blockIdx.x;
    float* dst = g_Wg + (size_t)n * KGX;
    for (int k = threadIdx.x; k < KG; k += 256) dst[k]       = W_ih[(size_t)n*KG + k];
    for (int k = threadIdx.x; k < HH; k += 256) dst[KG + k]  = W_hh[(size_t)n*HH + k];
}

// combined [att_h_w ; sag_w] : 2560 x 512 and fused bias
__global__ void build_wh(const float* __restrict__ ah_w, const float* __restrict__ ah_b,
                         const float* __restrict__ sag_w, const float* __restrict__ sag_b)
{
    int n = blockIdx.x;
    const float* src = (n < AA) ? (ah_w + (size_t)n*HH) : (sag_w + (size_t)(n-AA)*HH);
    float* dst = g_Whg + (size_t)n * HH;
    for (int k = threadIdx.x; k < HH; k += 256) dst[k] = src[k];
    if (threadIdx.x == 0) g_bias_fused[n] = (n < AA) ? ah_b[n] : sag_b[n - AA];
}

__global__ void mean_kernel(const float* __restrict__ img)
{
    int b  = blockIdx.y;
    int ch = blockIdx.x * 256 + threadIdx.x;
    int ord = g_order[b];
    const float* base = img + (size_t)ord * PP * ENC + ch;
    float acc = 0.f;
#pragma unroll 4
    for (int p = 0; p < PP; p++) acc += base[(size_t)p * ENC];
    g_mean[b*ENC + ch] = acc * (1.0f / (float)PP);
}

__global__ void h0copy_kernel()
{
    int b = blockIdx.x;
    g_gatesin[(size_t)b*KGX + KG + threadIdx.x] = g_h[b*HH + threadIdx.x];
}

// ================= tf32x3 tensor-core GEMM =================
// C[m,n] = sum_k A[m,k] * W[n,k] (+bias). A: MxK row-major, W: NxK row-major.
// Block tile 64x64, BK=16, 256 threads (8 warps as 2x4, warp tile 32x16).
// MODE: 0 plain store to C. 1 fused hid/gs split. 2 logits masked store.
#define M_PLAIN  0
#define M_FUSEDH 1
#define M_LOGITS 2

template<int MODE, bool MASKED>
__global__ void __launch_bounds__(256)
mma_gemm(const float* __restrict__ A, const float* __restrict__ W,
         const float* __restrict__ bias, float* __restrict__ C,
         int M, int N, int K, int t, float* __restrict__ out2)
{
    const int m0 = blockIdx.y * 64;
    const int n0 = blockIdx.x * 64;
    if (MASKED && g_predlen[m0] <= t) return;

    // [buf][comp][16*72]: comp 0=A_hi 1=A_lo 2=W_hi 3=W_lo
    __shared__ uint32_t sm[2][4][16*72];

    const int tid  = threadIdx.x;
    const int lane = tid & 31;
    const int warp = tid >> 5;
    const int wm   = warp >> 2;         // 0..1  (m: 32 rows each)
    const int wn   = warp & 3;          // 0..3  (n: 16 cols each)
    const int r    = lane >> 2;         // 0..7
    const int c    = lane & 3;          // 0..3

    const int ar = tid >> 2;            // 0..63 (load row)
    const int ak = (tid & 3) << 2;      // 0,4,8,12 (load k)

    float4 acc[2][2];
#pragma unroll
    for (int i = 0; i < 2; i++)
#pragma unroll
        for (int j = 0; j < 2; j++) acc[i][j] = make_float4(0.f, 0.f, 0.f, 0.f);

    float4 av, wv;
    auto g_load = [&](int k0) {
        av = *(const float4*)(A + (size_t)(m0 + ar) * K + k0 + ak);
        int n = n0 + ar;
        wv = (n < N) ? *(const float4*)(W + (size_t)n * K + k0 + ak)
                     : make_float4(0.f, 0.f, 0.f, 0.f);
    };
    auto s_store = [&](int buf) {
        float a4[4] = {av.x, av.y, av.z, av.w};
        float w4[4] = {wv.x, wv.y, wv.z, wv.w};
#pragma unroll
        for (int j = 0; j < 4; j++) {
            int id = IDX(ak + j, ar);
            uint32_t ahi = f2tf32(a4[j]);
            float    alo = a4[j] - __uint_as_float(ahi);
            sm[buf][0][id] = ahi;
            sm[buf][1][id] = f2tf32(alo);
            uint32_t whi = f2tf32(w4[j]);
            float    wlo = w4[j] - __uint_as_float(whi);
            sm[buf][2][id] = whi;
            sm[buf][3][id] = f2tf32(wlo);
        }
    };

    g_load(0);
    s_store(0);
    __syncthreads();

    int cur = 0;
    const int nk = K / 16;
    for (int kt = 0; kt < nk; kt++) {
        if (kt + 1 < nk) g_load((kt + 1) * 16);

        const uint32_t* Ah = sm[cur][0];
        const uint32_t* Al = sm[cur][1];
        const uint32_t* Wh = sm[cur][2];
        const uint32_t* Wl = sm[cur][3];

#pragma unroll
        for (int k8 = 0; k8 < 16; k8 += 8) {
            uint32_t ah[2][4], al[2][4], bh[2][2], bl[2][2];
#pragma unroll
            for (int mt = 0; mt < 2; mt++) {
                int m = wm*32 + mt*16 + r;
                int i00 = IDX(k8 + c,     m);
                int i01 = IDX(k8 + c,     m + 8);
                int i10 = IDX(k8 + c + 4, m);
                int i11 = IDX(k8 + c + 4, m + 8);
                ah[mt][0] = Ah[i00]; ah[mt][1] = Ah[i01];
                ah[mt][2] = Ah[i10]; ah[mt][3] = Ah[i11];
                al[mt][0] = Al[i00]; al[mt][1] = Al[i01];
                al[mt][2] = Al[i10]; al[mt][3] = Al[i11];
            }
#pragma unroll
            for (int nt = 0; nt < 2; nt++) {
                int n = wn*16 + nt*8 + r;
                int j0 = IDX(k8 + c,     n);
                int j1 = IDX(k8 + c + 4, n);
                bh[nt][0] = Wh[j0]; bh[nt][1] = Wh[j1];
                bl[nt][0] = Wl[j0]; bl[nt][1] = Wl[j1];
            }
#pragma unroll
            for (int mt = 0; mt < 2; mt++)
#pragma unroll
                for (int nt = 0; nt < 2; nt++) {
                    mma_tf32(acc[mt][nt], ah[mt], bh[nt]);   // hi*hi
                    mma_tf32(acc[mt][nt], ah[mt], bl[nt]);   // hi*lo
                    mma_tf32(acc[mt][nt], al[mt], bh[nt]);   // lo*hi
                }
        }

        if (kt + 1 < nk) {
            s_store(cur ^ 1);
            __syncthreads();
            cur ^= 1;
        }
    }

    auto epi = [&](int m, int n, float v) {
        if (n >= N) return;
        v += bias[n];
        if (MODE == M_PLAIN) {
            C[(size_t)m * N + n] = v;
        } else if (MODE == M_FUSEDH) {
            if (n < AA) C[(size_t)m * AA + n] = v;
            else        out2[(size_t)m * ENC + (n - AA)] = sigf(v);
        } else { // M_LOGITS
            if (g_predlen[m] > t) C[((size_t)m * TT + t) * VV + n] = v;
        }
    };

#pragma unroll
    for (int mt = 0; mt < 2; mt++)
#pragma unroll
        for (int nt = 0; nt < 2; nt++) {
            int row = m0 + wm*32 + mt*16 + r;
            int col = n0 + wn*16 + nt*8 + 2*c;
            float4 d = acc[mt][nt];
            epi(row,     col,     d.x);
            epi(row,     col + 1, d.y);
            epi(row + 8, col,     d.z);
            epi(row + 8, col + 1, d.w);
        }
}

// ---------------- x_t gather ----------------
__global__ void xt_kernel(const float* __restrict__ emb, int t)
{
    int b = blockIdx.x;
    if (g_predlen[b] <= t) return;
    int cap = g_caps[b*SS + t];
    g_gatesin[(size_t)b*KGX + threadIdx.x] = emb[(size_t)cap * EE + threadIdx.x];
}

// ---------------- fused attention scores + softmax ----------------
__global__ void attn_kernel(const float* __restrict__ fw, const float* __restrict__ fb, int t)
{
    int b = blockIdx.x;
    if (g_predlen[b] <= t) return;
    __shared__ float s_fw[AA], s_hid[AA], s_e[200], s_r[8];
    int tid = threadIdx.x;
    s_fw[tid]       = fw[tid];
    s_fw[tid + 256] = fw[tid + 256];
    s_hid[tid]       = g_hidatt[b*AA + tid];
    s_hid[tid + 256] = g_hidatt[b*AA + tid + 256];
    __syncthreads();

    int warp = tid >> 5, lane = tid & 31;
    int ord = g_order[b];
    const float* base = g_encatt + (size_t)ord * PP * AA;
    for (int p = warp; p < PP; p += 8) {
        const float* row = base + (size_t)p * AA;
        float acc = 0.f;
#pragma unroll
        for (int a = lane; a < AA; a += 32)
            acc += fmaxf(row[a] + s_hid[a], 0.f) * s_fw[a];
        for (int o = 16; o; o >>= 1) acc += __shfl_xor_sync(0xFFFFFFFFu, acc, o);
        if (!lane) s_e[p] = acc;
    }
    __syncthreads();

    float fbv = fb[0];
    float v = (tid < PP) ? (s_e[tid] + fbv) : -1e30f;
    float m = v;
    for (int o = 16; o; o >>= 1) m = fmaxf(m, __shfl_xor_sync(0xFFFFFFFFu, m, o));
    if (!lane) s_r[warp] = m;
    __syncthreads();
    float bm = s_r[0];
    for (int i = 1; i < 8; i++) bm = fmaxf(bm, s_r[i]);
    __syncthreads();
    float ex = (tid < PP) ? expf(v - bm) : 0.f;
    float sm = ex;
    for (int o = 16; o; o >>= 1) sm += __shfl_xor_sync(0xFFFFFFFFu, sm, o);
    if (!lane) s_r[warp] = sm;
    __syncthreads();
    float bs = 0.f;
    for (int i = 0; i < 8; i++) bs += s_r[i];
    if (tid < PP) g_alpha[b*PP + tid] = ex / bs;
}

// ---------------- gated context ----------------
__global__ void ctx_kernel(const float* __restrict__ img, int t)
{
    int b = blockIdx.y;
    if (g_predlen[b] <= t) return;
    __shared__ float s_a[PP];
    int tid = threadIdx.x;
    if (tid < PP) s_a[tid] = g_alpha[b*PP + tid];
    __syncthreads();
    int c = blockIdx.x * 256 + tid;
    int ord = g_order[b];
    const float* base = img + (size_t)ord * PP * ENC + c;
    float acc = 0.f;
#pragma unroll 4
    for (int p = 0; p < PP; p++) acc += s_a[p] * base[(size_t)p * ENC];
    g_gatesin[(size_t)b*KGX + EE + c] = acc * g_gs[b*ENC + c];
}

// ---------------- LSTM cell ----------------
__global__ void cell_kernel(int t)
{
    int b = blockIdx.x;
    if (g_predlen[b] <= t) return;
    int j = threadIdx.x;
    const float* g = g_gates + (size_t)b * 4*HH;
    float ig = sigf(g[j]);
    float fg = sigf(g[j + HH]);
    float gg = tanhf(g[j + 2*HH]);
    float og = sigf(g[j + 3*HH]);
    float c  = fg * g_c[b*HH + j] + ig * gg;
    float h  = og * tanhf(c);
    g_c[b*HH + j] = c;
    g_h[b*HH + j] = h;
    g_hnew[b*HH + j] = h;
    g_gatesin[(size_t)b*KGX + KG + j] = h;
}

// ---------------- launch ----------------
extern "C" void kernel_launch(void* const* d_in, const int* in_sizes, int n_in,
                              void* d_out, int out_size)
{
    const float* img   = (const float*)d_in[0];
    const int*   caps  = (const int*)d_in[1];
    const int*   clen  = (const int*)d_in[2];
    const float* emb   = (const float*)d_in[3];
    const float* W_ih  = (const float*)d_in[4];
    const float* W_hh  = (const float*)d_in[5];
    const float* b_ih  = (const float*)d_in[6];
    const float* b_hh  = (const float*)d_in[7];
    const float* ec_w  = (const float*)d_in[8];
    const float* ec_b  = (const float*)d_in[9];
    const float* eh_w  = (const float*)d_in[10];
    const float* eh_b  = (const float*)d_in[11];
    const float* sag_w = (const float*)d_in[12];
    const float* sag_b = (const float*)d_in[13];
    const float* ae_w  = (const float*)d_in[14];
    const float* ae_b  = (const float*)d_in[15];
    const float* ah_w  = (const float*)d_in[16];
    const float* ah_b  = (const float*)d_in[17];
    const float* af_w  = (const float*)d_in[18];
    const float* af_b  = (const float*)d_in[19];
    const float* fc_w  = (const float*)d_in[20];
    const float* fc_b  = (const float*)d_in[21];
    float* out = (float*)d_out;

    float *p_mean, *p_h, *p_c, *p_hid, *p_gs, *p_gin, *p_gates, *p_hnew,
          *p_encatt, *p_bg, *p_bf, *p_Wg, *p_Whg;
    cudaGetSymbolAddress((void**)&p_mean,   g_mean);
    cudaGetSymbolAddress((void**)&p_h,      g_h);
    cudaGetSymbolAddress((void**)&p_c,      g_c);
    cudaGetSymbolAddress((void**)&p_hid,    g_hidatt);
    cudaGetSymbolAddress((void**)&p_gs,     g_gs);
    cudaGetSymbolAddress((void**)&p_gin,    g_gatesin);
    cudaGetSymbolAddress((void**)&p_gates,  g_gates);
    cudaGetSymbolAddress((void**)&p_hnew,   g_hnew);
    cudaGetSymbolAddress((void**)&p_encatt, g_encatt);
    cudaGetSymbolAddress((void**)&p_bg,     g_bias_gates);
    cudaGetSymbolAddress((void**)&p_bf,     g_bias_fused);
    cudaGetSymbolAddress((void**)&p_Wg,     g_Wg);
    cudaGetSymbolAddress((void**)&p_Whg,    g_Whg);

    cudaMemsetAsync(d_out, 0, (size_t)out_size * sizeof(float));

    setup_kernel<<<1, 256>>>(caps, clen, b_ih, b_hh, out);
    build_wg<<<4*HH, 256>>>(W_ih, W_hh);
    build_wh<<<KG, 256>>>(ah_w, ah_b, sag_w, sag_b);
    mean_kernel<<<dim3(ENC/256, BB), 256>>>(img);

    // h0 / c0  (M=256, N=512, K=2048)
    mma_gemm<M_PLAIN, false><<<dim3(HH/64, BB/64), 256>>>(p_mean, eh_w, eh_b, p_h, BB, HH, ENC, 0, nullptr);
    mma_gemm<M_PLAIN, false><<<dim3(HH/64, BB/64), 256>>>(p_mean, ec_w, ec_b, p_c, BB, HH, ENC, 0, nullptr);
    h0copy_kernel<<<BB, HH>>>();

    // enc_att precompute (M=50176, N=512, K=2048), original image order
    mma_gemm<M_PLAIN, false><<<dim3(AA/64, (BB*PP)/64), 256>>>(img, ae_w, ae_b, p_encatt,
                                                               BB*PP, AA, ENC, 0, nullptr);

    for (int t = 0; t < TT; t++) {
        // fused: hid_att (plain) + gs (sigmoid)  (M=256, N=2560, K=512)
        mma_gemm<M_FUSEDH, true><<<dim3(KG/64, BB/64), 256>>>(p_h, p_Whg, p_bf, p_hid, BB, KG, HH, t, p_gs);
        xt_kernel<<<BB, EE>>>(emb, t);
        attn_kernel<<<BB, 256>>>(af_w, af_b, t);
        ctx_kernel<<<dim3(ENC/256, BB), 256>>>(img, t);
        // gates = [x|ctx|h] @ Wg^T + (b_ih+b_hh)  (M=256, N=2048, K=3072)
        mma_gemm<M_PLAIN, true><<<dim3((4*HH)/64, BB/64), 256>>>(p_gin, p_Wg, p_bg, p_gates, BB, 4*HH, KGX, t, nullptr);
        cell_kernel<<<BB, HH>>>(t);
        // logits (M=256, N=10000, K=512)
        mma_gemm<M_LOGITS, true><<<dim3((VV+63)/64, BB/64), 256>>>(p_hnew, fc_w, fc_b, out + OUT_PRED_OFF,
                                                                   BB, VV, HH, t, nullptr);
    }
}